// round 6
// baseline (speedup 1.0000x reference)
#include <cuda_runtime.h>

// KAConvComparision: rational (Pade) per-tap conv.
// x: (4,16,64,64) f32   nums: (32,16,3,3,6) f32   denoms: (32,16,3,3,4) f32
// out: (4,32,64,64) f32
// out[b,f,y,x] = sum_{c,k} P_{f,c,k}(v) / (1 + |Qs_{f,c,k}(v)|)
//
// R6: PPX=4 (tile 64x8, blockDim 128), 2-pass channel staging to stay under
// 48KB static smem (32.6KB -> 6 blocks/SM = 24 warps/SM), pk2 hoisted per
// (c,ky), packed filter-pair accumulate epilogue. FFMA2 Horner core.

#define CC 16
#define HH 64
#define WW 64
#define FF 32
#define TS_Y 8
#define XR   10          // tile rows + halo
#define XW   66          // tile cols + halo
#define CP   8           // channels per staging pass

typedef unsigned long long u64;

__device__ __forceinline__ u64 pk2(float lo, float hi) {
    u64 r; asm("mov.b64 %0, {%1, %2};" : "=l"(r) : "f"(lo), "f"(hi)); return r;
}
__device__ __forceinline__ void upk2(u64 v, float& lo, float& hi) {
    asm("mov.b64 {%0, %1}, %2;" : "=f"(lo), "=f"(hi) : "l"(v));
}
__device__ __forceinline__ u64 fma2(u64 a, u64 b, u64 c) {
    u64 d; asm("fma.rn.f32x2 %0, %1, %2, %3;" : "=l"(d) : "l"(a), "l"(b), "l"(c)); return d;
}
__device__ __forceinline__ u64 mul2(u64 a, u64 b) {
    u64 d; asm("mul.rn.f32x2 %0, %1, %2;" : "=l"(d) : "l"(a), "l"(b)); return d;
}
__device__ __forceinline__ float rcpf(float a) {
    float r; asm("rcp.approx.f32 %0, %1;" : "=f"(r) : "f"(a)); return r;
}

__global__ __launch_bounds__(128, 6)
void kaconv_kernel(const float* __restrict__ x,
                   const float* __restrict__ nums,
                   const float* __restrict__ denoms,
                   float* __restrict__ out)
{
    // x tile: 8 channels (per pass) x 10 rows x 66 cols.  21.12 KB
    __shared__ float xs[CP * XR * XW];
    // coeffs for ONE filter pair, all 16 channels: cf[(ck*10+j)*2+h]. 11.52 KB
    __shared__ __align__(16) float cf[CC * 9 * 10 * 2];

    const int tid  = threadIdx.x;
    const int trow = blockIdx.x;          // 8 row tiles (full width)
    const int fp   = blockIdx.y;          // 16 filter pairs
    const int b    = blockIdx.z;

    const int y0 = trow * TS_Y - 1;

    // ---- stage packed coefficient pairs (once) ----
    for (int i = tid; i < CC * 9 * 20; i += 128) {
        int h  = i & 1;            // filter within pair
        int t  = i >> 1;
        int j  = t % 10;           // 0..5 = a0..a5, 6..9 = b1..b4
        int ck = t / 10;           // c*9 + k
        int f  = fp * 2 + h;
        float v;
        if (j < 6) v = nums[(f * CC * 9 + ck) * 6 + j];
        else       v = denoms[(f * CC * 9 + ck) * 4 + (j - 6)];
        cf[i] = v;
    }

    const int tx = tid & 15;    // 16 col groups of 4 px
    const int ty = tid >> 4;    // 8 rows

    u64 accp[4];                // packed (f0,f1) accumulators per pixel
    #pragma unroll
    for (int p = 0; p < 4; p++) accp[p] = 0ull;

    const float* xb = &xs[ty * XW + tx * 4];
    const ulonglong2* cb = (const ulonglong2*)cf;

    #pragma unroll 1
    for (int pass = 0; pass < 2; pass++) {
        if (pass) __syncthreads();   // xs reuse: wait for previous compute
        // ---- stage 8 channels (zero-padded halo) ----
        for (int i = tid; i < CP * XR * XW; i += 128) {
            int c8  = i / (XR * XW);
            int rem = i - c8 * (XR * XW);
            int r   = rem / XW;
            int col = rem - r * XW;
            int gy = y0 + r, gx = col - 1;
            float v = 0.0f;
            if ((unsigned)gy < (unsigned)HH && (unsigned)gx < (unsigned)WW)
                v = x[((b * CC + pass * CP + c8) * HH + gy) * WW + gx];
            xs[i] = v;
        }
        __syncthreads();

        #pragma unroll 1
        for (int c8 = 0; c8 < CP; c8++) {
            const int c = pass * CP + c8;
            const float* xc = xb + c8 * (XR * XW);
            const ulonglong2* cc_ = cb + c * 45;   // 9 records x 5 u2
            #pragma unroll
            for (int ky = 0; ky < 3; ky++) {
                // 6 consecutive cols: cover kx 0..2 x px 0..3
                float2 A = *(const float2*)(xc + ky * XW);
                float2 Bv = *(const float2*)(xc + ky * XW + 2);
                float2 Cv = *(const float2*)(xc + ky * XW + 4);
                u64 wv[6];
                wv[0] = pk2(A.x,  A.x);
                wv[1] = pk2(A.y,  A.y);
                wv[2] = pk2(Bv.x, Bv.x);
                wv[3] = pk2(Bv.y, Bv.y);
                wv[4] = pk2(Cv.x, Cv.x);
                wv[5] = pk2(Cv.y, Cv.y);
                #pragma unroll
                for (int kx = 0; kx < 3; kx++) {
                    const ulonglong2* cp = cc_ + (ky * 3 + kx) * 5;
                    ulonglong2 q0 = cp[0];  // {a0,a1} packed pairs
                    ulonglong2 q1 = cp[1];  // {a2,a3}
                    ulonglong2 q2 = cp[2];  // {a4,a5}
                    ulonglong2 q3 = cp[3];  // {b1,b2}
                    ulonglong2 q4 = cp[4];  // {b3,b4}
                    #pragma unroll
                    for (int p = 0; p < 4; p++) {
                        u64 w = wv[kx + p];
                        u64 P = fma2(q2.y, w, q2.x);
                        P = fma2(P, w, q1.y);
                        P = fma2(P, w, q1.x);
                        P = fma2(P, w, q0.y);
                        P = fma2(P, w, q0.x);
                        u64 T = fma2(q4.y, w, q4.x);
                        T = fma2(T, w, q3.y);
                        T = fma2(T, w, q3.x);
                        u64 Qs = mul2(T, w);
                        float ql, qh;
                        upk2(Qs, ql, qh);
                        float r0 = rcpf(1.0f + fabsf(ql));
                        float r1 = rcpf(1.0f + fabsf(qh));
                        u64 rp = pk2(r0, r1);
                        accp[p] = fma2(P, rp, accp[p]);
                    }
                }
            }
        }
    }

    // ---- unpack & write out (float4 per filter) ----
    float o0x, o1x, o0y, o1y, o0z, o1z, o0w, o1w;
    upk2(accp[0], o0x, o1x);
    upk2(accp[1], o0y, o1y);
    upk2(accp[2], o0z, o1z);
    upk2(accp[3], o0w, o1w);

    const int gy  = trow * TS_Y + ty;
    const int gxb = tx * 4;
    const int f0  = fp * 2;
    *(float4*)&out[((b * FF + f0    ) * HH + gy) * WW + gxb] =
        make_float4(o0x, o0y, o0z, o0w);
    *(float4*)&out[((b * FF + f0 + 1) * HH + gy) * WW + gxb] =
        make_float4(o1x, o1y, o1z, o1w);
}

extern "C" void kernel_launch(void* const* d_in, const int* in_sizes, int n_in,
                              void* d_out, int out_size)
{
    const float* x      = (const float*)d_in[0];
    const float* nums   = (const float*)d_in[1];
    const float* denoms = (const float*)d_in[2];
    float* out          = (float*)d_out;

    dim3 grid(8, FF / 2, 4);   // (8 row tiles, 16 filter pairs, batch)
    kaconv_kernel<<<grid, 128>>>(x, nums, denoms, out);
}

// round 8
// speedup vs baseline: 1.0888x; 1.0888x over previous
#include <cuda_runtime.h>

// KAConvComparision: rational (Pade) per-tap conv.
// x: (4,16,64,64) f32   nums: (32,16,3,3,6) f32   denoms: (32,16,3,3,4) f32
// out: (4,32,64,64) f32
// out[b,f,y,x] = sum_{c,k} P_{f,c,k}(v) / (1 + |Qs_{f,c,k}(v)|)
//
// R7: R5 geometry (tile 32x8, 1024 blocks, blockDim 128 -- grid supply is the
// occupancy binder) + CP=8 two-pass channel staging (smem 33.3->22.4KB) +
// launch_bounds(128,7) so 7 blocks/SM fit in the register file + packed
// filter-pair accumulate + pk2 hoisted per (c,ky). FFMA2 Horner core.

#define CC 16
#define HH 64
#define WW 64
#define FF 32
#define TS_X 32
#define TS_Y 8
#define XR   10          // tile rows + halo
#define XW   34          // tile cols + halo (even -> float2 aligned)
#define CP   8           // channels per staging pass

typedef unsigned long long u64;

__device__ __forceinline__ u64 pk2(float lo, float hi) {
    u64 r; asm("mov.b64 %0, {%1, %2};" : "=l"(r) : "f"(lo), "f"(hi)); return r;
}
__device__ __forceinline__ void upk2(u64 v, float& lo, float& hi) {
    asm("mov.b64 {%0, %1}, %2;" : "=f"(lo), "=f"(hi) : "l"(v));
}
__device__ __forceinline__ u64 fma2(u64 a, u64 b, u64 c) {
    u64 d; asm("fma.rn.f32x2 %0, %1, %2, %3;" : "=l"(d) : "l"(a), "l"(b), "l"(c)); return d;
}
__device__ __forceinline__ u64 mul2(u64 a, u64 b) {
    u64 d; asm("mul.rn.f32x2 %0, %1, %2;" : "=l"(d) : "l"(a), "l"(b)); return d;
}
__device__ __forceinline__ float rcpf(float a) {
    float r; asm("rcp.approx.f32 %0, %1;" : "=f"(r) : "f"(a)); return r;
}

__global__ __launch_bounds__(128, 7)
void kaconv_kernel(const float* __restrict__ x,
                   const float* __restrict__ nums,
                   const float* __restrict__ denoms,
                   float* __restrict__ out)
{
    // x tile: 8 channels (per pass) x 10 rows x 34 cols.  10.88 KB
    __shared__ float xs[CP * XR * XW];
    // coeffs for ONE filter pair, all 16 channels: cf[(ck*10+j)*2+h]. 11.52 KB
    __shared__ __align__(16) float cf[CC * 9 * 10 * 2];

    const int tid  = threadIdx.x;
    const int tcol = blockIdx.x & 1;      // 2 col tiles
    const int trow = blockIdx.x >> 1;     // 8 row tiles
    const int fp   = blockIdx.y;          // 16 filter pairs
    const int b    = blockIdx.z;

    const int x0 = tcol * TS_X - 1;
    const int y0 = trow * TS_Y - 1;

    // ---- stage packed coefficient pairs (once) ----
    for (int i = tid; i < CC * 9 * 20; i += 128) {
        int h  = i & 1;            // filter within pair
        int t  = i >> 1;
        int j  = t % 10;           // 0..5 = a0..a5, 6..9 = b1..b4
        int ck = t / 10;           // c*9 + k
        int f  = fp * 2 + h;
        float v;
        if (j < 6) v = nums[(f * CC * 9 + ck) * 6 + j];
        else       v = denoms[(f * CC * 9 + ck) * 4 + (j - 6)];
        cf[i] = v;
    }

    const int tx = tid & 15;    // 16 col groups of 2 px
    const int ty = tid >> 4;    // 8 rows

    u64 acc0 = 0ull, acc1 = 0ull;   // packed (f0,f1) accumulators per pixel

    const float* xb = &xs[ty * XW + tx * 2];
    const ulonglong2* cb = (const ulonglong2*)cf;

    #pragma unroll 1
    for (int pass = 0; pass < 2; pass++) {
        if (pass) __syncthreads();   // xs reuse: wait for previous compute
        // ---- stage 8 channels (zero-padded halo) ----
        for (int i = tid; i < CP * XR * XW; i += 128) {
            int c8  = i / (XR * XW);
            int rem = i - c8 * (XR * XW);
            int r   = rem / XW;
            int col = rem - r * XW;
            int gy = y0 + r, gx = x0 + col;
            float v = 0.0f;
            if ((unsigned)gy < (unsigned)HH && (unsigned)gx < (unsigned)WW)
                v = x[((b * CC + pass * CP + c8) * HH + gy) * WW + gx];
            xs[i] = v;
        }
        __syncthreads();

        #pragma unroll 1
        for (int c8 = 0; c8 < CP; c8++) {
            const int c = pass * CP + c8;
            const float* xc = xb + c8 * (XR * XW);
            const ulonglong2* cc_ = cb + c * 45;   // 9 records x 5 u2
            #pragma unroll
            for (int ky = 0; ky < 3; ky++) {
                // 4 consecutive cols: cover kx 0..2 x px 0..1
                float2 A = *(const float2*)(xc + ky * XW);
                float2 Bv = *(const float2*)(xc + ky * XW + 2);
                u64 wv[4];
                wv[0] = pk2(A.x,  A.x);
                wv[1] = pk2(A.y,  A.y);
                wv[2] = pk2(Bv.x, Bv.x);
                wv[3] = pk2(Bv.y, Bv.y);
                #pragma unroll
                for (int kx = 0; kx < 3; kx++) {
                    const ulonglong2* cp = cc_ + (ky * 3 + kx) * 5;
                    ulonglong2 q0 = cp[0];  // {a0,a1} packed pairs
                    ulonglong2 q1 = cp[1];  // {a2,a3}
                    ulonglong2 q2 = cp[2];  // {a4,a5}
                    ulonglong2 q3 = cp[3];  // {b1,b2}
                    ulonglong2 q4 = cp[4];  // {b3,b4}
                    // pixel 0
                    {
                        u64 w = wv[kx];
                        u64 P = fma2(q2.y, w, q2.x);
                        P = fma2(P, w, q1.y);
                        P = fma2(P, w, q1.x);
                        P = fma2(P, w, q0.y);
                        P = fma2(P, w, q0.x);
                        u64 T = fma2(q4.y, w, q4.x);
                        T = fma2(T, w, q3.y);
                        T = fma2(T, w, q3.x);
                        u64 Qs = mul2(T, w);
                        float ql, qh;
                        upk2(Qs, ql, qh);
                        float r0 = rcpf(1.0f + fabsf(ql));
                        float r1 = rcpf(1.0f + fabsf(qh));
                        acc0 = fma2(P, pk2(r0, r1), acc0);
                    }
                    // pixel 1
                    {
                        u64 w = wv[kx + 1];
                        u64 P = fma2(q2.y, w, q2.x);
                        P = fma2(P, w, q1.y);
                        P = fma2(P, w, q1.x);
                        P = fma2(P, w, q0.y);
                        P = fma2(P, w, q0.x);
                        u64 T = fma2(q4.y, w, q4.x);
                        T = fma2(T, w, q3.y);
                        T = fma2(T, w, q3.x);
                        u64 Qs = mul2(T, w);
                        float ql, qh;
                        upk2(Qs, ql, qh);
                        float r0 = rcpf(1.0f + fabsf(ql));
                        float r1 = rcpf(1.0f + fabsf(qh));
                        acc1 = fma2(P, pk2(r0, r1), acc1);
                    }
                }
            }
        }
    }

    // ---- unpack & write out (float2 per filter, gxb even) ----
    float o00, o10, o01, o11;
    upk2(acc0, o00, o10);
    upk2(acc1, o01, o11);

    const int gy  = trow * TS_Y + ty;
    const int gxb = tcol * TS_X + tx * 2;
    const int f0  = fp * 2;
    *(float2*)&out[((b * FF + f0    ) * HH + gy) * WW + gxb] = make_float2(o00, o01);
    *(float2*)&out[((b * FF + f0 + 1) * HH + gy) * WW + gxb] = make_float2(o10, o11);
}

extern "C" void kernel_launch(void* const* d_in, const int* in_sizes, int n_in,
                              void* d_out, int out_size)
{
    const float* x      = (const float*)d_in[0];
    const float* nums   = (const float*)d_in[1];
    const float* denoms = (const float*)d_in[2];
    float* out          = (float*)d_out;

    dim3 grid(16, FF / 2, 4);   // (2 col x 8 row tiles, 16 filter pairs, batch)
    kaconv_kernel<<<grid, 128>>>(x, nums, denoms, out);
}